// round 3
// baseline (speedup 1.0000x reference)
#include <cuda_runtime.h>
#include <stdint.h>

#define N_NODES 50000
#define N_EDGES 800000
#define D 256

// ---------------- device scratch (no dynamic allocation allowed) ----------------
__device__ float g_src[(size_t)N_NODES * D];   // SRC = x@W_src + b_src  (51.2 MB, L2-resident)
__device__ int   g_deg[N_NODES];
__device__ int   g_rowptr[N_NODES + 1];
__device__ int   g_cursor[N_NODES];
__device__ int   g_esrc[N_EDGES];              // CSR payload: source node per incoming edge
__device__ int   g_is64;                        // 1 if edge_index is int64, 0 if int32

// ---------------- K0: detect edge_index dtype on device ----------------
// int64 data (values < 2^31) viewed as int32 has zero high words at odd slots.
__global__ void k_detect(const int* __restrict__ ei32) {
    if (threadIdx.x == 0 && blockIdx.x == 0) {
        int nz = 0;
        #pragma unroll 8
        for (int i = 0; i < 128; i++) nz |= ei32[2 * i + 1];
        g_is64 = (nz == 0) ? 1 : 0;
    }
}

__device__ __forceinline__ int load_idx(const void* ei, int is64, int pos) {
    if (is64) return (int)((const long long*)ei)[pos];
    return ((const int*)ei)[pos];
}

// ---------------- K1: zero degree histogram ----------------
__global__ void k_zero_deg() {
    int i = blockIdx.x * blockDim.x + threadIdx.x;
    if (i < N_NODES) g_deg[i] = 0;
}

// ---------------- K2: degree histogram over destination (col) ----------------
__global__ void k_hist(const void* __restrict__ ei) {
    int e = blockIdx.x * blockDim.x + threadIdx.x;
    if (e < N_EDGES) {
        int col = load_idx(ei, g_is64, N_EDGES + e);
        if ((unsigned)col < (unsigned)N_NODES)
            atomicAdd(&g_deg[col], 1);
    }
}

// ---------------- K3: single-block exclusive scan -> rowptr, cursor ----------------
__global__ void k_scan() {
    __shared__ int sums[1024];
    const int CH = (N_NODES + 1023) / 1024;  // 49
    int t = threadIdx.x;
    int base = t * CH;

    int s = 0;
    #pragma unroll 4
    for (int i = 0; i < CH; i++) {
        int idx = base + i;
        if (idx < N_NODES) s += g_deg[idx];
    }
    sums[t] = s;
    __syncthreads();

    // Hillis-Steele inclusive scan over the 1024 chunk sums
    for (int off = 1; off < 1024; off <<= 1) {
        int v = (t >= off) ? sums[t - off] : 0;
        __syncthreads();
        sums[t] += v;
        __syncthreads();
    }
    int run = (t == 0) ? 0 : sums[t - 1];

    for (int i = 0; i < CH; i++) {
        int idx = base + i;
        if (idx < N_NODES) {
            g_rowptr[idx] = run;
            g_cursor[idx] = run;
            run += g_deg[idx];
        }
    }
    if (t == 1023) g_rowptr[N_NODES] = run;   // = total edge count
}

// ---------------- K4: counting-sort fill of CSR buckets ----------------
__global__ void k_fill(const void* __restrict__ ei) {
    int e = blockIdx.x * blockDim.x + threadIdx.x;
    if (e < N_EDGES) {
        int is64 = g_is64;
        int row = load_idx(ei, is64, e);
        int col = load_idx(ei, is64, N_EDGES + e);
        if ((unsigned)row < (unsigned)N_NODES && (unsigned)col < (unsigned)N_NODES) {
            int pos = atomicAdd(&g_cursor[col], 1);
            if ((unsigned)pos < (unsigned)N_EDGES) g_esrc[pos] = row;
        }
    }
}

// ---------------- K5: fused triple GEMM ----------------
// SRC            = x @ W_src  + b_src                        -> g_src
// d_out (OUT0)   = x @ W_self + b_self - deg*(x@W_dst+b_dst) -> d_out
// 64x64 block tile, BK=16, 256 threads, 4x4 micro-tile, 3 accumulator sets.
#define BM 64
#define BN 64
#define BK 16

__global__ __launch_bounds__(256)
void k_gemm(const float* __restrict__ x,
            const float* __restrict__ Wsrc, const float* __restrict__ bsrc,
            const float* __restrict__ Wdst, const float* __restrict__ bdst,
            const float* __restrict__ Wself, const float* __restrict__ bself,
            float* __restrict__ out) {
    __shared__ __align__(16) float As[BK][BM];
    __shared__ __align__(16) float Bs[3][BK][BN];

    const int tid = threadIdx.x;
    const int tx = tid & 15;     // 0..15 -> 4 output columns each
    const int ty = tid >> 4;     // 0..15 -> 4 output rows each

    const int rowBase = blockIdx.y * BM;
    const int n0 = blockIdx.x * BN;

    // A-load mapping: each thread loads one float4 along K
    const int aRow = tid >> 2;          // 0..63
    const int aK4  = (tid & 3) * 4;     // 0,4,8,12
    // B-load mapping: each thread loads one float4 per matrix
    const int bK   = tid >> 4;          // 0..15
    const int bJ4  = (tid & 15) * 4;    // 0..60

    const float* Ws[3] = {Wsrc, Wdst, Wself};

    float acc_s[4][4] = {};
    float acc_d[4][4] = {};
    float acc_f[4][4] = {};

    for (int k0 = 0; k0 < D; k0 += BK) {
        // load A tile (x), transposed into As[k][m]
        float4 av = make_float4(0.f, 0.f, 0.f, 0.f);
        int gr = rowBase + aRow;
        if (gr < N_NODES)
            av = *reinterpret_cast<const float4*>(&x[(size_t)gr * D + k0 + aK4]);
        As[aK4 + 0][aRow] = av.x;
        As[aK4 + 1][aRow] = av.y;
        As[aK4 + 2][aRow] = av.z;
        As[aK4 + 3][aRow] = av.w;

        // load the three B tiles
        #pragma unroll
        for (int m = 0; m < 3; m++) {
            float4 bv = *reinterpret_cast<const float4*>(&Ws[m][(size_t)(k0 + bK) * D + n0 + bJ4]);
            *reinterpret_cast<float4*>(&Bs[m][bK][bJ4]) = bv;
        }
        __syncthreads();

        #pragma unroll
        for (int kk = 0; kk < BK; kk++) {
            float4 a  = *reinterpret_cast<const float4*>(&As[kk][ty * 4]);
            float4 b0 = *reinterpret_cast<const float4*>(&Bs[0][kk][tx * 4]);
            float4 b1 = *reinterpret_cast<const float4*>(&Bs[1][kk][tx * 4]);
            float4 b2 = *reinterpret_cast<const float4*>(&Bs[2][kk][tx * 4]);
            const float ar[4] = {a.x, a.y, a.z, a.w};
            const float bs0[4] = {b0.x, b0.y, b0.z, b0.w};
            const float bs1[4] = {b1.x, b1.y, b1.z, b1.w};
            const float bs2[4] = {b2.x, b2.y, b2.z, b2.w};
            #pragma unroll
            for (int i = 0; i < 4; i++) {
                #pragma unroll
                for (int j = 0; j < 4; j++) {
                    acc_s[i][j] = fmaf(ar[i], bs0[j], acc_s[i][j]);
                    acc_d[i][j] = fmaf(ar[i], bs1[j], acc_d[i][j]);
                    acc_f[i][j] = fmaf(ar[i], bs2[j], acc_f[i][j]);
                }
            }
        }
        __syncthreads();
    }

    // epilogue
    const int c0 = n0 + tx * 4;
    const float4 bsrc4  = *reinterpret_cast<const float4*>(&bsrc[c0]);
    const float4 bdst4  = *reinterpret_cast<const float4*>(&bdst[c0]);
    const float4 bself4 = *reinterpret_cast<const float4*>(&bself[c0]);
    const float bsr[4] = {bsrc4.x, bsrc4.y, bsrc4.z, bsrc4.w};
    const float bds[4] = {bdst4.x, bdst4.y, bdst4.z, bdst4.w};
    const float bsf[4] = {bself4.x, bself4.y, bself4.z, bself4.w};

    #pragma unroll
    for (int i = 0; i < 4; i++) {
        int v = rowBase + ty * 4 + i;
        if (v >= N_NODES) break;
        float degf = (float)(g_rowptr[v + 1] - g_rowptr[v]);
        float4 so, oo;
        float* sp = (float*)&so;
        float* op = (float*)&oo;
        #pragma unroll
        for (int j = 0; j < 4; j++) {
            float sv = acc_s[i][j] + bsr[j];
            sp[j] = sv;
            op[j] = acc_f[i][j] + bsf[j] - degf * (acc_d[i][j] + bds[j]);
        }
        *reinterpret_cast<float4*>(&g_src[(size_t)v * D + c0]) = so;
        *reinterpret_cast<float4*>(&out[(size_t)v * D + c0]) = oo;
    }
}

// ---------------- K6: per-node gather reduce: out[v] += sum_{nbr} SRC[nbr] ----------------
__global__ __launch_bounds__(256)
void k_reduce(float* __restrict__ out) {
    const int v = blockIdx.x;
    const int dim = threadIdx.x;       // 256 dims, one per thread
    const int s = g_rowptr[v];
    const int e = g_rowptr[v + 1];

    __shared__ int nbr[512];

    float acc = 0.f;
    for (int base = s; base < e; base += 512) {
        int cnt = min(512, e - base);
        for (int i = threadIdx.x; i < cnt; i += 256) nbr[i] = g_esrc[base + i];
        __syncthreads();
        int i = 0;
        for (; i + 4 <= cnt; i += 4) {
            float x0 = g_src[(size_t)nbr[i + 0] * D + dim];
            float x1 = g_src[(size_t)nbr[i + 1] * D + dim];
            float x2 = g_src[(size_t)nbr[i + 2] * D + dim];
            float x3 = g_src[(size_t)nbr[i + 3] * D + dim];
            acc += (x0 + x1) + (x2 + x3);
        }
        for (; i < cnt; i++) acc += g_src[(size_t)nbr[i] * D + dim];
        __syncthreads();
    }
    if (e > s) out[(size_t)v * D + dim] += acc;
}

// ---------------- launch ----------------
extern "C" void kernel_launch(void* const* d_in, const int* in_sizes, int n_in,
                              void* d_out, int out_size) {
    const float* x     = (const float*)d_in[0];
    const void*  ei    = d_in[1];
    const float* Wsrc  = (const float*)d_in[2];
    const float* bsrc  = (const float*)d_in[3];
    const float* Wdst  = (const float*)d_in[4];
    const float* bdst  = (const float*)d_in[5];
    const float* Wself = (const float*)d_in[6];
    const float* bself = (const float*)d_in[7];
    float* out = (float*)d_out;

    k_detect<<<1, 32>>>((const int*)ei);
    k_zero_deg<<<(N_NODES + 255) / 256, 256>>>();
    k_hist<<<(N_EDGES + 255) / 256, 256>>>(ei);
    k_scan<<<1, 1024>>>();
    k_fill<<<(N_EDGES + 255) / 256, 256>>>(ei);

    dim3 ggrid(D / BN, (N_NODES + BM - 1) / BM);  // (4, 782)
    k_gemm<<<ggrid, 256>>>(x, Wsrc, bsrc, Wdst, bdst, Wself, bself, out);

    k_reduce<<<N_NODES, 256>>>(out);
}